// round 14
// baseline (speedup 1.0000x reference)
#include <cuda_runtime.h>

#define N_NODES 100000
#define N_EDGES 3200000

// ---- persistent device scratch (no allocations allowed) ----
// g_deg is zero-initialized at module load; k_finish re-zeroes it every call.
__device__ int   g_deg [N_NODES];
__device__ float g_dinv[N_NODES];
__device__ float g_xn  [N_NODES * 4];   // x * dinv  (src-normalized features)
__device__ float g_agg [N_NODES * 4];   // layer-1 accumulator, init = xn (self loop)
__device__ float g_tn  [N_NODES * 2];   // t * dinv  (src-normalized layer-2 features)

// Vectorized no-return global reductions (one L2 message per 2/4 floats).
__device__ __forceinline__ void red_add_v4(float* p, float a, float b, float c, float d) {
    asm volatile("red.global.add.v4.f32 [%0], {%1,%2,%3,%4};"
                 :: "l"(p), "f"(a), "f"(b), "f"(c), "f"(d) : "memory");
}
__device__ __forceinline__ void red_add_v2(float* p, float a, float b) {
    asm volatile("red.global.add.v2.f32 [%0], {%1,%2};"
                 :: "l"(p), "f"(a), "f"(b) : "memory");
}
__device__ __forceinline__ void red_add_u32(int* p) {
    asm volatile("red.global.add.u32 [%0], 1;" :: "l"(p) : "memory");
}

#define EDGE_GRID 1184   // 8 blocks/SM * 148 SMs: persistent edge kernels

// K1: degree of dst endpoints. Persistent grid-stride; index stream __ldcs.
__global__ void k_deg(const int* __restrict__ dst) {
    cudaGridDependencySynchronize();
    int stride = gridDim.x * blockDim.x;
    for (int i = blockIdx.x * blockDim.x + threadIdx.x; i < N_EDGES / 4; i += stride) {
        int4 d = __ldcs(&reinterpret_cast<const int4*>(dst)[i]);
        red_add_u32(&g_deg[d.x]);
        red_add_u32(&g_deg[d.y]);
        red_add_u32(&g_deg[d.z]);
        red_add_u32(&g_deg[d.w]);
    }
}

// K2: dinv = rsqrt(deg+1);  xn = x*dinv;  agg init = xn (layer-1 self loop)
__global__ void k_dinv_xn(const float* __restrict__ x) {
    int i = blockIdx.x * blockDim.x + threadIdx.x;
    if (i >= N_NODES) { cudaGridDependencySynchronize(); return; }
    float4 xv = reinterpret_cast<const float4*>(x)[i];   // independent input
    cudaGridDependencySynchronize();                     // wait for k_deg
    float di = rsqrtf((float)(g_deg[i] + 1));
    g_dinv[i] = di;
    float4 xn = make_float4(xv.x * di, xv.y * di, xv.z * di, xv.w * di);
    reinterpret_cast<float4*>(g_xn)[i]  = xn;
    reinterpret_cast<float4*>(g_agg)[i] = xn;
}

// K3: layer-1 edges: agg[dst] += xn[src]  (dst factor deferred).
// Persistent grid-stride.
__global__ void k_l1_edges(const int* __restrict__ src, const int* __restrict__ dst) {
    cudaGridDependencySynchronize();                     // wait for k_dinv_xn
    const float4* xv = reinterpret_cast<const float4*>(g_xn);
    int stride = gridDim.x * blockDim.x;
    for (int i = blockIdx.x * blockDim.x + threadIdx.x; i < N_EDGES / 4; i += stride) {
        int4 s = __ldcs(&reinterpret_cast<const int4*>(src)[i]);
        int4 d = __ldcs(&reinterpret_cast<const int4*>(dst)[i]);
        float4 v0 = xv[s.x];
        float4 v1 = xv[s.y];
        float4 v2 = xv[s.z];
        float4 v3 = xv[s.w];
        red_add_v4(&g_agg[4 * d.x], v0.x, v0.y, v0.z, v0.w);
        red_add_v4(&g_agg[4 * d.y], v1.x, v1.y, v1.z, v1.w);
        red_add_v4(&g_agg[4 * d.z], v2.x, v2.y, v2.z, v2.w);
        red_add_v4(&g_agg[4 * d.w], v3.x, v3.y, v3.z, v3.w);
    }
}

// K4: per-node transform (1 node/thread — occupancy beats ILP here, R13).
//   a = dinv*agg; h = relu(a@W1+b1); t = h@W2; tn = t*dinv;
//   out init = tn (layer-2 self loop pre-dst-scale)
__global__ void k_xform(const float* __restrict__ W1, const float* __restrict__ b1,
                        const float* __restrict__ W2,
                        float* __restrict__ out) {
    int v = blockIdx.x * blockDim.x + threadIdx.x;
    if (v >= N_NODES) { cudaGridDependencySynchronize(); return; }
    cudaGridDependencySynchronize();                     // wait for k_l1_edges
    float di = g_dinv[v];
    float4 ag = reinterpret_cast<const float4*>(g_agg)[v];
    float a0 = ag.x * di;
    float a1 = ag.y * di;
    float a2 = ag.z * di;
    float a3 = ag.w * di;

    float t0 = 0.f, t1 = 0.f;
    #pragma unroll
    for (int j = 0; j < 16; j++) {
        float h = a0 * W1[j] + a1 * W1[16 + j] + a2 * W1[32 + j] + a3 * W1[48 + j] + b1[j];
        h = fmaxf(h, 0.f);
        t0 += h * W2[2 * j];
        t1 += h * W2[2 * j + 1];
    }
    float tn0 = t0 * di, tn1 = t1 * di;
    reinterpret_cast<float2*>(g_tn)[v] = make_float2(tn0, tn1);
    reinterpret_cast<float2*>(out)[v]  = make_float2(tn0, tn1);  // self-loop init
}

// K5: layer-2 edges: out[dst] += tn[src]  (dst factor deferred).
// Persistent grid-stride.
__global__ void k_l2_edges(const int* __restrict__ src, const int* __restrict__ dst,
                           float* __restrict__ out) {
    cudaGridDependencySynchronize();                     // wait for k_xform
    const float2* tv = reinterpret_cast<const float2*>(g_tn);
    int stride = gridDim.x * blockDim.x;
    for (int i = blockIdx.x * blockDim.x + threadIdx.x; i < N_EDGES / 4; i += stride) {
        int4 s = __ldcs(&reinterpret_cast<const int4*>(src)[i]);
        int4 d = __ldcs(&reinterpret_cast<const int4*>(dst)[i]);
        float2 t0 = tv[s.x];
        float2 t1 = tv[s.y];
        float2 t2 = tv[s.z];
        float2 t3 = tv[s.w];
        red_add_v2(&out[2 * d.x], t0.x, t0.y);
        red_add_v2(&out[2 * d.y], t1.x, t1.y);
        red_add_v2(&out[2 * d.z], t2.x, t2.y);
        red_add_v2(&out[2 * d.w], t3.x, t3.y);
    }
}

// K6: apply deferred dst factor + bias:  out = out*dinv + b2.
//     Also re-zero g_deg for the next call.
__global__ void k_finish(float* __restrict__ out, const float* __restrict__ b2) {
    int v = blockIdx.x * blockDim.x + threadIdx.x;
    if (v >= N_NODES) { cudaGridDependencySynchronize(); return; }
    cudaGridDependencySynchronize();                     // wait for k_l2_edges
    float di = g_dinv[v];
    float2 o = reinterpret_cast<float2*>(out)[v];
    reinterpret_cast<float2*>(out)[v] =
        make_float2(o.x * di + b2[0], o.y * di + b2[1]);
    g_deg[v] = 0;
}

// PDL launch helper.
template <typename... Args>
static inline void launch_pdl(void (*kern)(Args...), int grid, int block, Args... args) {
    cudaLaunchConfig_t cfg = {};
    cfg.gridDim  = dim3(grid, 1, 1);
    cfg.blockDim = dim3(block, 1, 1);
    cudaLaunchAttribute attr[1];
    attr[0].id = cudaLaunchAttributeProgrammaticStreamSerialization;
    attr[0].val.programmaticStreamSerializationAllowed = 1;
    cfg.attrs = attr;
    cfg.numAttrs = 1;
    cudaLaunchKernelEx(&cfg, kern, args...);
}

extern "C" void kernel_launch(void* const* d_in, const int* in_sizes, int n_in,
                              void* d_out, int out_size) {
    const float* x   = (const float*)d_in[0];     // [N, 4]
    const int*   ei  = (const int*)  d_in[1];     // [2, E]
    const float* W1  = (const float*)d_in[2];     // [4, 16]
    const float* b1  = (const float*)d_in[3];     // [16]
    const float* W2  = (const float*)d_in[4];     // [16, 2]
    const float* b2  = (const float*)d_in[5];     // [2]
    float* out = (float*)d_out;                   // [N, 2]

    const int* src = ei;
    const int* dst = ei + N_EDGES;

    const int TB = 256;
    int nodeBlocks = (N_NODES + TB - 1) / TB;

    launch_pdl(k_deg,      EDGE_GRID,  TB, dst);
    launch_pdl(k_dinv_xn,  nodeBlocks, TB, x);
    launch_pdl(k_l1_edges, EDGE_GRID,  TB, src, dst);
    launch_pdl(k_xform,    nodeBlocks, TB, W1, b1, W2, out);
    launch_pdl(k_l2_edges, EDGE_GRID,  TB, src, dst, out);
    launch_pdl(k_finish,   nodeBlocks, TB, out, b2);
}

// round 15
// speedup vs baseline: 1.0492x; 1.0492x over previous
#include <cuda_runtime.h>

#define N_NODES 100000
#define N_EDGES 3200000

// ---- persistent device scratch (no allocations allowed) ----
// g_deg is zero-initialized at module load; k_finish re-zeroes it every call.
__device__ int   g_deg [N_NODES];
__device__ float g_dinv[N_NODES];
__device__ float g_xn  [N_NODES * 4];   // x * dinv  (src-normalized features)
__device__ float g_agg [N_NODES * 4];   // layer-1 accumulator, init = xn (self loop)
__device__ float g_tn  [N_NODES * 2];   // t * dinv  (src-normalized layer-2 features)

// Vectorized no-return global reductions (one L2 message per 2/4 floats).
__device__ __forceinline__ void red_add_v4(float* p, float a, float b, float c, float d) {
    asm volatile("red.global.add.v4.f32 [%0], {%1,%2,%3,%4};"
                 :: "l"(p), "f"(a), "f"(b), "f"(c), "f"(d) : "memory");
}
__device__ __forceinline__ void red_add_v2(float* p, float a, float b) {
    asm volatile("red.global.add.v2.f32 [%0], {%1,%2};"
                 :: "l"(p), "f"(a), "f"(b) : "memory");
}
__device__ __forceinline__ void red_add_u32(int* p) {
    asm volatile("red.global.add.u32 [%0], 1;" :: "l"(p) : "memory");
}

// K1: degree of dst endpoints. One int4 of indices per thread, loaded BEFORE
// the grid-dep sync (PDL prologue overlap with predecessor drain).
__global__ void k_deg(const int* __restrict__ dst) {
    int i = blockIdx.x * blockDim.x + threadIdx.x;
    if (i < N_EDGES / 4) {
        int4 d = __ldcs(&reinterpret_cast<const int4*>(dst)[i]);
        cudaGridDependencySynchronize();
        red_add_u32(&g_deg[d.x]);
        red_add_u32(&g_deg[d.y]);
        red_add_u32(&g_deg[d.z]);
        red_add_u32(&g_deg[d.w]);
    } else {
        cudaGridDependencySynchronize();
    }
}

// K2: dinv = rsqrt(deg+1);  xn = x*dinv;  agg init = xn (layer-1 self loop)
__global__ void k_dinv_xn(const float* __restrict__ x) {
    int i = blockIdx.x * blockDim.x + threadIdx.x;
    if (i >= N_NODES) { cudaGridDependencySynchronize(); return; }
    float4 xv = reinterpret_cast<const float4*>(x)[i];   // independent input
    cudaGridDependencySynchronize();                     // wait for k_deg
    float di = rsqrtf((float)(g_deg[i] + 1));
    g_dinv[i] = di;
    float4 xn = make_float4(xv.x * di, xv.y * di, xv.z * di, xv.w * di);
    reinterpret_cast<float4*>(g_xn)[i]  = xn;
    reinterpret_cast<float4*>(g_agg)[i] = xn;
}

// K3: layer-1 edges: agg[dst] += xn[src]  (dst factor deferred)
// Index loads before sync (PDL overlap); gathers default-cached (hot-node reuse).
__global__ void k_l1_edges(const int* __restrict__ src, const int* __restrict__ dst) {
    int i = blockIdx.x * blockDim.x + threadIdx.x;
    if (i >= N_EDGES / 4) { cudaGridDependencySynchronize(); return; }
    int4 s = __ldcs(&reinterpret_cast<const int4*>(src)[i]);  // independent inputs
    int4 d = __ldcs(&reinterpret_cast<const int4*>(dst)[i]);
    cudaGridDependencySynchronize();                     // wait for k_dinv_xn
    const float4* xv = reinterpret_cast<const float4*>(g_xn);

    float4 v0 = xv[s.x];
    float4 v1 = xv[s.y];
    float4 v2 = xv[s.z];
    float4 v3 = xv[s.w];
    red_add_v4(&g_agg[4 * d.x], v0.x, v0.y, v0.z, v0.w);
    red_add_v4(&g_agg[4 * d.y], v1.x, v1.y, v1.z, v1.w);
    red_add_v4(&g_agg[4 * d.z], v2.x, v2.y, v2.z, v2.w);
    red_add_v4(&g_agg[4 * d.w], v3.x, v3.y, v3.z, v3.w);
}

// K4: per-node transform (1 node/thread; occupancy beats ILP here, R13).
//   a = dinv*agg; h = relu(a@W1+b1); t = h@W2; tn = t*dinv;
//   out init = tn (layer-2 self loop pre-dst-scale)
__global__ void k_xform(const float* __restrict__ W1, const float* __restrict__ b1,
                        const float* __restrict__ W2,
                        float* __restrict__ out) {
    int v = blockIdx.x * blockDim.x + threadIdx.x;
    if (v >= N_NODES) { cudaGridDependencySynchronize(); return; }
    cudaGridDependencySynchronize();                     // wait for k_l1_edges
    float di = g_dinv[v];
    float4 ag = reinterpret_cast<const float4*>(g_agg)[v];
    float a0 = ag.x * di;
    float a1 = ag.y * di;
    float a2 = ag.z * di;
    float a3 = ag.w * di;

    float t0 = 0.f, t1 = 0.f;
    #pragma unroll
    for (int j = 0; j < 16; j++) {
        float h = a0 * W1[j] + a1 * W1[16 + j] + a2 * W1[32 + j] + a3 * W1[48 + j] + b1[j];
        h = fmaxf(h, 0.f);
        t0 += h * W2[2 * j];
        t1 += h * W2[2 * j + 1];
    }
    float tn0 = t0 * di, tn1 = t1 * di;
    reinterpret_cast<float2*>(g_tn)[v] = make_float2(tn0, tn1);
    reinterpret_cast<float2*>(out)[v]  = make_float2(tn0, tn1);  // self-loop init
}

// K5: layer-2 edges: out[dst] += tn[src]  (dst factor deferred)
__global__ void k_l2_edges(const int* __restrict__ src, const int* __restrict__ dst,
                           float* __restrict__ out) {
    int i = blockIdx.x * blockDim.x + threadIdx.x;
    if (i >= N_EDGES / 4) { cudaGridDependencySynchronize(); return; }
    int4 s = __ldcs(&reinterpret_cast<const int4*>(src)[i]);  // independent inputs
    int4 d = __ldcs(&reinterpret_cast<const int4*>(dst)[i]);
    cudaGridDependencySynchronize();                     // wait for k_xform
    const float2* tv = reinterpret_cast<const float2*>(g_tn);

    float2 t0 = tv[s.x];
    float2 t1 = tv[s.y];
    float2 t2 = tv[s.z];
    float2 t3 = tv[s.w];
    red_add_v2(&out[2 * d.x], t0.x, t0.y);
    red_add_v2(&out[2 * d.y], t1.x, t1.y);
    red_add_v2(&out[2 * d.z], t2.x, t2.y);
    red_add_v2(&out[2 * d.w], t3.x, t3.y);
}

// K6: apply deferred dst factor + bias:  out = out*dinv + b2.
//     Also re-zero g_deg for the next call.
__global__ void k_finish(float* __restrict__ out, const float* __restrict__ b2) {
    int v = blockIdx.x * blockDim.x + threadIdx.x;
    if (v >= N_NODES) { cudaGridDependencySynchronize(); return; }
    cudaGridDependencySynchronize();                     // wait for k_l2_edges
    float di = g_dinv[v];
    float2 o = reinterpret_cast<float2*>(out)[v];
    reinterpret_cast<float2*>(out)[v] =
        make_float2(o.x * di + b2[0], o.y * di + b2[1]);
    g_deg[v] = 0;
}

// PDL launch helper.
template <typename... Args>
static inline void launch_pdl(void (*kern)(Args...), int grid, int block, Args... args) {
    cudaLaunchConfig_t cfg = {};
    cfg.gridDim  = dim3(grid, 1, 1);
    cfg.blockDim = dim3(block, 1, 1);
    cudaLaunchAttribute attr[1];
    attr[0].id = cudaLaunchAttributeProgrammaticStreamSerialization;
    attr[0].val.programmaticStreamSerializationAllowed = 1;
    cfg.attrs = attr;
    cfg.numAttrs = 1;
    cudaLaunchKernelEx(&cfg, kern, args...);
}

extern "C" void kernel_launch(void* const* d_in, const int* in_sizes, int n_in,
                              void* d_out, int out_size) {
    const float* x   = (const float*)d_in[0];     // [N, 4]
    const int*   ei  = (const int*)  d_in[1];     // [2, E]
    const float* W1  = (const float*)d_in[2];     // [4, 16]
    const float* b1  = (const float*)d_in[3];     // [16]
    const float* W2  = (const float*)d_in[4];     // [16, 2]
    const float* b2  = (const float*)d_in[5];     // [2]
    float* out = (float*)d_out;                   // [N, 2]

    const int* src = ei;
    const int* dst = ei + N_EDGES;

    const int TBE = 256;   // edge kernels (proven optimum)
    const int TBN = 128;   // node kernels: 2x blocks for latency-bound grid-limited work
    int nodeBlocks = (N_NODES + TBN - 1) / TBN;
    int edgeBlocks = (N_EDGES / 4 + TBE - 1) / TBE;

    launch_pdl(k_deg,      edgeBlocks, TBE, dst);
    launch_pdl(k_dinv_xn,  nodeBlocks, TBN, x);
    launch_pdl(k_l1_edges, edgeBlocks, TBE, src, dst);
    launch_pdl(k_xform,    nodeBlocks, TBN, W1, b1, W2, out);
    launch_pdl(k_l2_edges, edgeBlocks, TBE, src, dst, out);
    launch_pdl(k_finish,   nodeBlocks, TBN, out, b2);
}

// round 16
// speedup vs baseline: 1.0687x; 1.0186x over previous
#include <cuda_runtime.h>

#define N_NODES 100000
#define N_EDGES 3200000

// ---- persistent device scratch (no allocations allowed) ----
// g_deg is zero-initialized at module load; k_finish re-zeroes it every call.
__device__ int   g_deg [N_NODES];
__device__ float g_dinv[N_NODES];
__device__ float g_xn  [N_NODES * 4];   // x * dinv  (src-normalized features)
__device__ float g_agg [N_NODES * 4];   // layer-1 accumulator, init = xn (self loop)
__device__ float g_tn  [N_NODES * 2];   // t * dinv  (src-normalized layer-2 features)

// Vectorized no-return global reductions (one L2 message per 2/4 floats).
__device__ __forceinline__ void red_add_v4(float* p, float a, float b, float c, float d) {
    asm volatile("red.global.add.v4.f32 [%0], {%1,%2,%3,%4};"
                 :: "l"(p), "f"(a), "f"(b), "f"(c), "f"(d) : "memory");
}
__device__ __forceinline__ void red_add_v2(float* p, float a, float b) {
    asm volatile("red.global.add.v2.f32 [%0], {%1,%2};"
                 :: "l"(p), "f"(a), "f"(b) : "memory");
}
__device__ __forceinline__ void red_add_u32(int* p) {
    asm volatile("red.global.add.u32 [%0], 1;" :: "l"(p) : "memory");
}

// K1: degree of dst endpoints. One int4 of indices per thread, loaded BEFORE
// the grid-dep sync (PDL prologue overlap with predecessor drain).
__global__ void k_deg(const int* __restrict__ dst) {
    int i = blockIdx.x * blockDim.x + threadIdx.x;
    if (i < N_EDGES / 4) {
        int4 d = __ldcs(&reinterpret_cast<const int4*>(dst)[i]);
        cudaGridDependencySynchronize();
        red_add_u32(&g_deg[d.x]);
        red_add_u32(&g_deg[d.y]);
        red_add_u32(&g_deg[d.z]);
        red_add_u32(&g_deg[d.w]);
    } else {
        cudaGridDependencySynchronize();
    }
}

// K2: dinv = rsqrt(deg+1);  xn = x*dinv;  agg init = xn (layer-1 self loop)
__global__ void k_dinv_xn(const float* __restrict__ x) {
    int i = blockIdx.x * blockDim.x + threadIdx.x;
    if (i >= N_NODES) { cudaGridDependencySynchronize(); return; }
    float4 xv = reinterpret_cast<const float4*>(x)[i];   // independent input
    cudaGridDependencySynchronize();                     // wait for k_deg
    float di = rsqrtf((float)(g_deg[i] + 1));
    g_dinv[i] = di;
    float4 xn = make_float4(xv.x * di, xv.y * di, xv.z * di, xv.w * di);
    reinterpret_cast<float4*>(g_xn)[i]  = xn;
    reinterpret_cast<float4*>(g_agg)[i] = xn;
}

// K3: layer-1 edges: agg[dst] += xn[src]  (dst factor deferred)
// Index loads before sync (PDL overlap); gathers default-cached (hot-node reuse).
__global__ void k_l1_edges(const int* __restrict__ src, const int* __restrict__ dst) {
    int i = blockIdx.x * blockDim.x + threadIdx.x;
    if (i >= N_EDGES / 4) { cudaGridDependencySynchronize(); return; }
    int4 s = __ldcs(&reinterpret_cast<const int4*>(src)[i]);  // independent inputs
    int4 d = __ldcs(&reinterpret_cast<const int4*>(dst)[i]);
    cudaGridDependencySynchronize();                     // wait for k_dinv_xn
    const float4* xv = reinterpret_cast<const float4*>(g_xn);

    float4 v0 = xv[s.x];
    float4 v1 = xv[s.y];
    float4 v2 = xv[s.z];
    float4 v3 = xv[s.w];
    red_add_v4(&g_agg[4 * d.x], v0.x, v0.y, v0.z, v0.w);
    red_add_v4(&g_agg[4 * d.y], v1.x, v1.y, v1.z, v1.w);
    red_add_v4(&g_agg[4 * d.z], v2.x, v2.y, v2.z, v2.w);
    red_add_v4(&g_agg[4 * d.w], v3.x, v3.y, v3.z, v3.w);
}

// K4: per-node transform (1 node/thread; occupancy beats ILP here, R13).
//   a = dinv*agg; h = relu(a@W1+b1); t = h@W2; tn = t*dinv;
//   out init = tn (layer-2 self loop pre-dst-scale)
__global__ void k_xform(const float* __restrict__ W1, const float* __restrict__ b1,
                        const float* __restrict__ W2,
                        float* __restrict__ out) {
    int v = blockIdx.x * blockDim.x + threadIdx.x;
    if (v >= N_NODES) { cudaGridDependencySynchronize(); return; }
    cudaGridDependencySynchronize();                     // wait for k_l1_edges
    float di = g_dinv[v];
    float4 ag = reinterpret_cast<const float4*>(g_agg)[v];
    float a0 = ag.x * di;
    float a1 = ag.y * di;
    float a2 = ag.z * di;
    float a3 = ag.w * di;

    float t0 = 0.f, t1 = 0.f;
    #pragma unroll
    for (int j = 0; j < 16; j++) {
        float h = a0 * W1[j] + a1 * W1[16 + j] + a2 * W1[32 + j] + a3 * W1[48 + j] + b1[j];
        h = fmaxf(h, 0.f);
        t0 += h * W2[2 * j];
        t1 += h * W2[2 * j + 1];
    }
    float tn0 = t0 * di, tn1 = t1 * di;
    reinterpret_cast<float2*>(g_tn)[v] = make_float2(tn0, tn1);
    reinterpret_cast<float2*>(out)[v]  = make_float2(tn0, tn1);  // self-loop init
}

// K5: layer-2 edges: out[dst] += tn[src]  (dst factor deferred)
__global__ void k_l2_edges(const int* __restrict__ src, const int* __restrict__ dst,
                           float* __restrict__ out) {
    int i = blockIdx.x * blockDim.x + threadIdx.x;
    if (i >= N_EDGES / 4) { cudaGridDependencySynchronize(); return; }
    int4 s = __ldcs(&reinterpret_cast<const int4*>(src)[i]);  // independent inputs
    int4 d = __ldcs(&reinterpret_cast<const int4*>(dst)[i]);
    cudaGridDependencySynchronize();                     // wait for k_xform
    const float2* tv = reinterpret_cast<const float2*>(g_tn);

    float2 t0 = tv[s.x];
    float2 t1 = tv[s.y];
    float2 t2 = tv[s.z];
    float2 t3 = tv[s.w];
    red_add_v2(&out[2 * d.x], t0.x, t0.y);
    red_add_v2(&out[2 * d.y], t1.x, t1.y);
    red_add_v2(&out[2 * d.z], t2.x, t2.y);
    red_add_v2(&out[2 * d.w], t3.x, t3.y);
}

// K6: apply deferred dst factor + bias:  out = out*dinv + b2.
//     Also re-zero g_deg for the next call.
__global__ void k_finish(float* __restrict__ out, const float* __restrict__ b2) {
    int v = blockIdx.x * blockDim.x + threadIdx.x;
    if (v >= N_NODES) { cudaGridDependencySynchronize(); return; }
    cudaGridDependencySynchronize();                     // wait for k_l2_edges
    float di = g_dinv[v];
    float2 o = reinterpret_cast<float2*>(out)[v];
    reinterpret_cast<float2*>(out)[v] =
        make_float2(o.x * di + b2[0], o.y * di + b2[1]);
    g_deg[v] = 0;
}

// PDL launch helper.
template <typename... Args>
static inline void launch_pdl(void (*kern)(Args...), int grid, int block, Args... args) {
    cudaLaunchConfig_t cfg = {};
    cfg.gridDim  = dim3(grid, 1, 1);
    cfg.blockDim = dim3(block, 1, 1);
    cudaLaunchAttribute attr[1];
    attr[0].id = cudaLaunchAttributeProgrammaticStreamSerialization;
    attr[0].val.programmaticStreamSerializationAllowed = 1;
    cfg.attrs = attr;
    cfg.numAttrs = 1;
    cudaLaunchKernelEx(&cfg, kern, args...);
}

extern "C" void kernel_launch(void* const* d_in, const int* in_sizes, int n_in,
                              void* d_out, int out_size) {
    const float* x   = (const float*)d_in[0];     // [N, 4]
    const int*   ei  = (const int*)  d_in[1];     // [2, E]
    const float* W1  = (const float*)d_in[2];     // [4, 16]
    const float* b1  = (const float*)d_in[3];     // [16]
    const float* W2  = (const float*)d_in[4];     // [16, 2]
    const float* b2  = (const float*)d_in[5];     // [2]
    float* out = (float*)d_out;                   // [N, 2]

    const int* src = ei;
    const int* dst = ei + N_EDGES;

    const int TBE = 512;   // edge kernels: same occupancy (4x512/SM), half the blocks
    const int TBN = 128;   // node kernels: latency-bound grid-limited work
    int nodeBlocks = (N_NODES + TBN - 1) / TBN;
    int edgeBlocks = (N_EDGES / 4 + TBE - 1) / TBE;

    launch_pdl(k_deg,      edgeBlocks, TBE, dst);
    launch_pdl(k_dinv_xn,  nodeBlocks, TBN, x);
    launch_pdl(k_l1_edges, edgeBlocks, TBE, src, dst);
    launch_pdl(k_xform,    nodeBlocks, TBN, W1, b1, W2, out);
    launch_pdl(k_l2_edges, edgeBlocks, TBE, src, dst, out);
    launch_pdl(k_finish,   nodeBlocks, TBN, out, b2);
}